// round 12
// baseline (speedup 1.0000x reference)
#include <cuda_runtime.h>
#include <cuda_bf16.h>
#include <cstdint>

// CRF forward scan, exp domain. FULLY WARP-AUTONOMOUS: 128 CTAs x 8 warps;
// warp (b,w) owns W rows {16b+2w, 16b+2w+1} over ALL 2048 cols.
// Zero __syncthreads in the loop, zero smem, no inter-warp coupling.
// Handoff: 8-deep slot ring of bf16 W. Each thread polls its 8x16B chunks
// (pending-mask retries) with canary 0xFFC0 per half; data >= 0 so sign bit
// == canary. Each 4B W word is written & cleared only by its owning warp
// (program order). Liveness: bounded canary tries + release-counter fallback.
// Row reduce: intra-warp butterfly (10 shuffles). Publish: one st.cg.u32.
// Normalizer: lagged sqrt-damped max over cols 0..255 (bit-identical in all
// warps), computed after publish, off the critical path.

#define T 2048
#define NBLK 128
#define NTHR 256
#define DEPTH 8
#define START_IDX 0
#define END_IDX 1
#define CANARY 0xFFC0FFC0u
#define POLL_TRIES 64
#define NWARPS_CHIP (NBLK * (NTHR / 32))   // 1024 producers per step

__device__ __align__(16) float g_Ef[(size_t)T * T];    // 16 MB exp(transitions)
__device__ __align__(16) unsigned g_W[DEPTH][T / 2];    // bf16-pair slot ring
__device__ unsigned g_cnt;                              // fallback counter

typedef unsigned long long ull;

__device__ __forceinline__ ull pack2f(float a, float b) {
    ull r; asm("mov.b64 %0, {%1, %2};" : "=l"(r) : "f"(a), "f"(b)); return r;
}
__device__ __forceinline__ ull pack2u(unsigned a, unsigned b) {
    ull r; asm("mov.b64 %0, {%1, %2};" : "=l"(r) : "r"(a), "r"(b)); return r;
}
__device__ __forceinline__ void unpack2f(ull p, float& a, float& b) {
    asm("mov.b64 {%0, %1}, %2;" : "=f"(a), "=f"(b) : "l"(p));
}
#define FMA2(acc, a, b) \
    asm("fma.rn.f32x2 %0, %1, %2, %0;" : "+l"(acc) : "l"(a), "l"(b))

__device__ __forceinline__ uint4 ld16cv(const unsigned* p) {
    uint4 w;
    asm volatile("ld.global.cv.v4.u32 {%0,%1,%2,%3}, [%4];"
                 : "=r"(w.x), "=r"(w.y), "=r"(w.z), "=r"(w.w) : "l"(p));
    return w;
}
__device__ __forceinline__ bool clean16(uint4 w) {
    return ((w.x | w.y | w.z | w.w) & 0x80008000u) == 0u;
}

// Wait for all 8 chunks of this thread's W view. Pending-mask retries,
// bounded tries, counter fallback. Always terminates.
__device__ __forceinline__ void wait128B(const unsigned* p, uint4 c[8],
                                         unsigned cnt_target) {
    unsigned pend = 0xffu;
    #pragma unroll
    for (int k = 0; k < 8; k++) {             // first round: full MLP
        uint4 w = ld16cv(p + k * 128);
        c[k] = w;
        if (clean16(w)) pend &= ~(1u << k);
    }
    #pragma unroll 1
    for (int i = 0; i < POLL_TRIES && pend; i++) {
        __nanosleep(32);
        #pragma unroll
        for (int k = 0; k < 8; k++) {
            if (pend & (1u << k)) {
                uint4 w = ld16cv(p + k * 128);
                if (clean16(w)) { c[k] = w; pend &= ~(1u << k); }
            }
        }
    }
    if (pend) {   // fallback: counter proves all producer stores visible
        unsigned cc;
        do {
            asm volatile("ld.acquire.gpu.global.u32 %0, [%1];"
                         : "=r"(cc) : "l"(&g_cnt));
            if (cc < cnt_target) __nanosleep(64);
        } while (cc < cnt_target);
        #pragma unroll
        for (int k = 0; k < 8; k++)
            if (pend & (1u << k)) c[k] = ld16cv(p + k * 128);
    }
}

__global__ void crf_init(const float* __restrict__ trans) {
    size_t idx = (size_t)blockIdx.x * blockDim.x + threadIdx.x;
    size_t stride = (size_t)gridDim.x * blockDim.x;
    for (size_t i = idx; i < (size_t)T * T; i += stride)
        g_Ef[i] = __expf(trans[i]);
    if (idx < T / 2) {
        g_W[0][idx] = (idx == 0) ? 0x00003F80u : 0u;   // W_0: bf16(1.0) at tag 0
        #pragma unroll
        for (int s = 1; s < DEPTH; s++) g_W[s][idx] = CANARY;
    }
    if (idx == 0) g_cnt = 0u;
}

__global__ void __launch_bounds__(NTHR, 1)
crf_main(const float* __restrict__ h, const float* __restrict__ trans,
         float* __restrict__ out, int S) {
    const int tid = threadIdx.x;
    const int wid = tid >> 5;
    const int ln = tid & 31;
    const int b = blockIdx.x;
    const int rA = b * 16 + 2 * wid;       // my warp's two rows
    const int myword = b * 8 + wid;        // u32 word index of my rows in W

    // E -> registers: rows rA, rA+1, cols {k*256 + ln*8 .. +7}, f32x2 packed
    ull eA[8][4], eB[8][4];
    #pragma unroll
    for (int k = 0; k < 8; k++) {
        const float4* pa = (const float4*)(g_Ef + (size_t)rA * T + k * 256 + ln * 8);
        const float4* pb = (const float4*)(g_Ef + (size_t)(rA + 1) * T + k * 256 + ln * 8);
        float4 a0 = pa[0], a1 = pa[1];
        float4 b0 = pb[0], b1 = pb[1];
        eA[k][0] = pack2f(a0.x, a0.y); eA[k][1] = pack2f(a0.z, a0.w);
        eA[k][2] = pack2f(a1.x, a1.y); eA[k][3] = pack2f(a1.z, a1.w);
        eB[k][0] = pack2f(b0.x, b0.y); eB[k][1] = pack2f(b0.z, b0.w);
        eB[k][2] = pack2f(b1.x, b1.y); eB[k][3] = pack2f(b1.z, b1.w);
    }

    double L = 0.0;
    float rinv = 1.0f;          // lagged normalizer (bit-identical everywhere)

    for (int t = 0; t < S; t++) {
        // emissions for my two rows (lane 0 only; adjacent -> one v2 load)
        float eemA = 1.0f, eemB = 1.0f;
        if (ln == 0) {
            float2 em = *(const float2*)(h + (size_t)t * T + rA);
            eemA = __expf(em.x);
            eemB = __expf(em.y);
        }

        // ---- wait for my 128B view of W_t (canary fast path + fallback) ----
        uint4 c[8];
        wait128B(g_W[t & 7] + ln * 4, c, (unsigned)NWARPS_CHIP * (unsigned)t);

        // ---- dot + (chunk-0) local max ----
        ull a0 = 0ULL, a1 = 0ULL, b0 = 0ULL, b1 = 0ULL;
        float mx = 0.0f;
        #pragma unroll
        for (int k = 0; k < 8; k++) {
            ull w0 = pack2u(c[k].x << 16, c[k].x & 0xffff0000u);
            ull w1 = pack2u(c[k].y << 16, c[k].y & 0xffff0000u);
            ull w2 = pack2u(c[k].z << 16, c[k].z & 0xffff0000u);
            ull w3 = pack2u(c[k].w << 16, c[k].w & 0xffff0000u);
            FMA2(a0, eA[k][0], w0); FMA2(a1, eA[k][1], w1);
            FMA2(a0, eA[k][2], w2); FMA2(a1, eA[k][3], w3);
            FMA2(b0, eB[k][0], w0); FMA2(b1, eB[k][1], w1);
            FMA2(b0, eB[k][2], w2); FMA2(b1, eB[k][3], w3);
            if (k == 0) {   // subset max: cols 0..255 (identical in all warps)
                float f0 = fmaxf(__uint_as_float(c[0].x << 16),
                                 __uint_as_float(c[0].x & 0xffff0000u));
                float f1 = fmaxf(__uint_as_float(c[0].y << 16),
                                 __uint_as_float(c[0].y & 0xffff0000u));
                float f2 = fmaxf(__uint_as_float(c[0].z << 16),
                                 __uint_as_float(c[0].z & 0xffff0000u));
                float f3 = fmaxf(__uint_as_float(c[0].w << 16),
                                 __uint_as_float(c[0].w & 0xffff0000u));
                mx = fmaxf(fmaxf(f0, f1), fmaxf(f2, f3));
            }
        }
        float xa, ya, xb, yb, x2, y2;
        unpack2f(a0, xa, ya); unpack2f(a1, x2, y2);
        float sA = (xa + ya) + (x2 + y2);
        unpack2f(b0, xb, yb); unpack2f(b1, x2, y2);
        float sB = (xb + yb) + (x2 + y2);

        // ---- intra-warp row reduce: 10 shuffles ----
        #pragma unroll
        for (int off = 16; off; off >>= 1) {
            sA += __shfl_xor_sync(0xffffffffu, sA, off);
            sB += __shfl_xor_sync(0xffffffffu, sB, off);
        }

        // ---- publish (lane 0), clear W_{t-2} word (lane 1) ----
        if (ln == 0) {
            float n0 = sA * rinv * eemA;
            float n1 = sB * rinv * eemB;
            unsigned pw;
            asm("cvt.rn.satfinite.bf16x2.f32 %0, %1, %2;"
                : "=r"(pw) : "f"(n1), "f"(n0));   // n1 -> hi, n0 -> lo
            asm volatile("st.global.cg.u32 [%0], %1;"
                         :: "l"(g_W[(t + 1) & 7] + myword), "r"(pw) : "memory");
            asm volatile("red.release.gpu.global.add.u32 [%0], %1;"
                         :: "l"(&g_cnt), "r"(1u) : "memory");
        } else if (ln == 1) {
            asm volatile("st.global.cg.u32 [%0], %1;"
                         :: "l"(g_W[(t + 6) & 7] + myword), "r"(CANARY) : "memory");
        }

        // ---- off-path: lagged sqrt-damped normalizer for step t+1 ----
        #pragma unroll
        for (int off = 16; off; off >>= 1)
            mx = fmaxf(mx, __shfl_xor_sync(0xffffffffu, mx, off));
        if (t < S - 1) {
            float lr = 0.5f * __logf(mx);    // bit-identical in every warp
            rinv = __expf(-lr);
            L += (double)lr;
        }
    }

    // ---- terminal: logZ = log(sum_j W_S[j]*exp(tr[END,j])) + L ----
    if (b == 0 && wid == 0) {
        uint4 c[8];
        wait128B(g_W[S & 7] + ln * 4, c, (unsigned)NWARPS_CHIP * (unsigned)S);
        float p = 0.0f;
        #pragma unroll
        for (int k = 0; k < 8; k++) {
            const float* te = trans + (size_t)END_IDX * T + k * 256 + ln * 8;
            p += __uint_as_float(c[k].x << 16)         * __expf(te[0]);
            p += __uint_as_float(c[k].x & 0xffff0000u) * __expf(te[1]);
            p += __uint_as_float(c[k].y << 16)         * __expf(te[2]);
            p += __uint_as_float(c[k].y & 0xffff0000u) * __expf(te[3]);
            p += __uint_as_float(c[k].z << 16)         * __expf(te[4]);
            p += __uint_as_float(c[k].z & 0xffff0000u) * __expf(te[5]);
            p += __uint_as_float(c[k].w << 16)         * __expf(te[6]);
            p += __uint_as_float(c[k].w & 0xffff0000u) * __expf(te[7]);
        }
        #pragma unroll
        for (int off = 16; off; off >>= 1)
            p += __shfl_xor_sync(0xffffffffu, p, off);
        if (ln == 0) out[0] = __logf(p) + (float)L;
    }
}

extern "C" void kernel_launch(void* const* d_in, const int* in_sizes, int n_in,
                              void* d_out, int out_size) {
    const float* h = (const float*)d_in[0];
    const float* trans = (const float*)d_in[1];
    float* out = (float*)d_out;
    int S = in_sizes[0] / T;

    crf_init<<<512, 256>>>(trans);
    crf_main<<<NBLK, NTHR>>>(h, trans, out, S);
}

// round 13
// speedup vs baseline: 2.3439x; 2.3439x over previous
#include <cuda_runtime.h>
#include <cuda_bf16.h>
#include <cstdint>

// CRF forward scan, exp domain. 128 persistent CTAs. (R9 topology — measured
// local optimum — with pipelined detection.)
// Fast path: consumers poll their OWN 16B of the bf16 W slot ring with ld.cv
// until no 16-bit half has the sign bit set (canary 0xFFC0). Detect == data
// load: ONE L2 round trip, no pre-dot barrier.
// R13: depth-3 pipelined poll (3 independent in-flight loads, ~150cy spacing,
// check oldest) instead of serial load+sleep. Any clean view is valid (slot
// data is write-once per step). Liveness: bounded tries + release-counter
// fallback (proven hang-free in R9).
// Normalizer: lagged sqrt-damped max by warp 1, fully off the critical path.

#define T 2048
#define ROWS 16
#define NBLK 128
#define NTHR 256
#define DEPTH 8
#define START_IDX 0
#define END_IDX 1
#define CANARY 0xFFC0FFC0u
#define POLL_TRIES 64

__device__ __align__(16) float g_Ef[(size_t)T * T];        // 16 MB exp(transitions)
__device__ __align__(16) unsigned g_W[DEPTH][T / 2];        // bf16-pair slot ring
__device__ unsigned g_cnt;                                  // fallback counter

typedef unsigned long long ull;

__device__ __forceinline__ ull pack2f(float a, float b) {
    ull r; asm("mov.b64 %0, {%1, %2};" : "=l"(r) : "f"(a), "f"(b)); return r;
}
__device__ __forceinline__ ull pack2u(unsigned a, unsigned b) {
    ull r; asm("mov.b64 %0, {%1, %2};" : "=l"(r) : "r"(a), "r"(b)); return r;
}
__device__ __forceinline__ void unpack2f(ull p, float& a, float& b) {
    asm("mov.b64 {%0, %1}, %2;" : "=f"(a), "=f"(b) : "l"(p));
}
#define FMA2(acc, a, b) \
    asm("fma.rn.f32x2 %0, %1, %2, %0;" : "+l"(acc) : "l"(a), "l"(b))

__device__ __forceinline__ uint4 ld16cv(const unsigned* p) {
    uint4 w;
    asm volatile("ld.global.cv.v4.u32 {%0,%1,%2,%3}, [%4];"
                 : "=r"(w.x), "=r"(w.y), "=r"(w.z), "=r"(w.w) : "l"(p));
    return w;
}
__device__ __forceinline__ bool clean16(uint4 w) {
    return ((w.x | w.y | w.z | w.w) & 0x80008000u) == 0u;
}
__device__ __forceinline__ void delay150(unsigned seed) {
    unsigned d = seed;                 // opaque ~150cy ALU chain
    #pragma unroll
    for (int i = 0; i < 72; i++) asm volatile("add.u32 %0,%0,1;" : "+r"(d));
    asm volatile("" :: "r"(d));
}

// Depth-3 pipelined canary poll + counter fallback. Always terminates.
__device__ __forceinline__ uint4 wait16B(const unsigned* p, unsigned cnt_target) {
    uint4 w0 = ld16cv(p);
    if (clean16(w0)) return w0;        // common fast case: already published
    delay150(w0.x);
    uint4 w1 = ld16cv(p);
    delay150(w1.x);
    #pragma unroll 1
    for (int i = 0; i < POLL_TRIES; i++) {
        uint4 w2 = ld16cv(p);          // keep 3 loads in flight
        if (clean16(w0)) return w0;    // oldest view; write-once => valid
        w0 = w1; w1 = w2;
        delay150(w2.x);
    }
    if (clean16(w0)) return w0;
    if (clean16(w1)) return w1;
    // Fallback: counter proves all producer stores are gpu-visible.
    unsigned c;
    do {
        asm volatile("ld.acquire.gpu.global.u32 %0, [%1];" : "=r"(c) : "l"(&g_cnt));
        if (c < cnt_target) __nanosleep(64);
    } while (c < cnt_target);
    return ld16cv(p);
}

__global__ void crf_init(const float* __restrict__ trans) {
    size_t idx = (size_t)blockIdx.x * blockDim.x + threadIdx.x;
    size_t stride = (size_t)gridDim.x * blockDim.x;
    for (size_t i = idx; i < (size_t)T * T; i += stride)
        g_Ef[i] = __expf(trans[i]);
    if (idx < T / 2) {
        g_W[0][idx] = (idx == 0) ? 0x00003F80u : 0u;   // W_0: bf16(1.0) at tag 0
        #pragma unroll
        for (int s = 1; s < DEPTH; s++) g_W[s][idx] = CANARY;
    }
    if (idx == 0) g_cnt = 0u;
}

__global__ void __launch_bounds__(NTHR, 1)
crf_main(const float* __restrict__ h, const float* __restrict__ trans,
         float* __restrict__ out, int S) {
    __shared__ __align__(16) float part[ROWS * NTHR];   // 16KB
    __shared__ __align__(16) float tmp2[ROWS * 16];
    __shared__ __align__(16) float mxs[2][NTHR];        // parity double-buffer
    __shared__ float sNorm[2];
    __shared__ double sL;

    const int tid = threadIdx.x;
    const int wid = tid >> 5;
    const int ln = tid & 31;
    const int b = blockIdx.x;
    const int r0 = b * ROWS;
    const int c0 = wid * 256 + ln * 8;    // my 8 columns
    const int wslot = c0 >> 1;            // word offset of my 16B in a slot

    if (tid == 0) { sNorm[0] = 1.0f; sNorm[1] = 1.0f; }

    // E -> registers: rows r0..r0+15 x my 8 cols, packed f32x2
    ull e64[ROWS][4];
    #pragma unroll
    for (int r = 0; r < ROWS; r++) {
        const float4* ep = (const float4*)(g_Ef + (size_t)(r0 + r) * T + c0);
        float4 a = ep[0], bb = ep[1];
        e64[r][0] = pack2f(a.x, a.y);
        e64[r][1] = pack2f(a.z, a.w);
        e64[r][2] = pack2f(bb.x, bb.y);
        e64[r][3] = pack2f(bb.z, bb.w);
    }

    double L = 0.0;   // meaningful only in tid 32

    for (int t = 0; t < S; t++) {
        // emissions (exp'd) for my row — off-path
        float eem = 1.0f;
        if (tid < ROWS) eem = __expf(__ldg(&h[(size_t)t * T + r0 + tid]));

        // ---- wait for my own 16B of W_t (pipelined canary, safe fallback) ----
        uint4 wv = wait16B(g_W[t & 7] + wslot, (unsigned)NBLK * (unsigned)t);

        ull w64[4];
        w64[0] = pack2u(wv.x << 16, wv.x & 0xffff0000u);
        w64[1] = pack2u(wv.y << 16, wv.y & 0xffff0000u);
        w64[2] = pack2u(wv.z << 16, wv.z & 0xffff0000u);
        w64[3] = pack2u(wv.w << 16, wv.w & 0xffff0000u);
        {   // thread-local max for the off-path normalizer — parity buffer
            float m0 = fmaxf(__uint_as_float(wv.x << 16), __uint_as_float(wv.x & 0xffff0000u));
            float m1 = fmaxf(__uint_as_float(wv.y << 16), __uint_as_float(wv.y & 0xffff0000u));
            float m2 = fmaxf(__uint_as_float(wv.z << 16), __uint_as_float(wv.z & 0xffff0000u));
            float m3 = fmaxf(__uint_as_float(wv.w << 16), __uint_as_float(wv.w & 0xffff0000u));
            mxs[t & 1][tid] = fmaxf(fmaxf(m0, m1), fmaxf(m2, m3));
        }

        // ---- dot: 16 rows x 8 cols, E in regs ----
        #pragma unroll
        for (int r = 0; r < ROWS; r++) {
            ull acc = 0ULL;
            FMA2(acc, e64[r][0], w64[0]);
            FMA2(acc, e64[r][1], w64[1]);
            FMA2(acc, e64[r][2], w64[2]);
            FMA2(acc, e64[r][3], w64[3]);
            float x, y;
            unpack2f(acc, x, y);
            part[r * NTHR + tid] = x + y;
        }
        __syncthreads();   // #1

        // ---- stage1: 256 partials/row -> 16/row ----
        {
            int rj = tid >> 4, cj = tid & 15;
            const float4* p4 = (const float4*)(part + rj * NTHR + cj * 16);
            float4 a = p4[0], b4 = p4[1], c4 = p4[2], d4 = p4[3];
            tmp2[rj * 16 + cj] =
                ((a.x + a.y) + (a.z + a.w)) + ((b4.x + b4.y) + (b4.z + b4.w)) +
                ((c4.x + c4.y) + (c4.z + c4.w)) + ((d4.x + d4.y) + (d4.z + d4.w));
        }
        __syncthreads();   // #2

        if (wid == 0) {
            if (ln < ROWS) {
                // ---- stage2: finish my row, scale, publish ----
                const float4* q4 = (const float4*)(tmp2 + ln * 16);
                float4 a = q4[0], b4 = q4[1], c4 = q4[2], d4 = q4[3];
                float rs =
                    ((a.x + a.y) + (a.z + a.w)) + ((b4.x + b4.y) + (b4.z + b4.w)) +
                    ((c4.x + c4.y) + (c4.z + c4.w)) + ((d4.x + d4.y) + (d4.z + d4.w));
                float n = rs * sNorm[t & 1] * eem;
                unsigned short us = __bfloat16_as_ushort(__float2bfloat16(n));
                unsigned short* dst = (unsigned short*)g_W[(t + 1) & 7] + (r0 + ln);
                asm volatile("st.global.cg.u16 [%0], %1;" :: "l"(dst), "h"(us) : "memory");
            }
            __syncwarp();   // order data stores before the release red
            if (ln == 16) {
                asm volatile("red.release.gpu.global.add.u32 [%0], %1;"
                             :: "l"(&g_cnt), "r"(1u) : "memory");
            } else if (ln == 17) {
                // clear my CTA's 32B in the slot holding W_{t-2}
                unsigned* cz = g_W[(t + 6) & 7] + (r0 >> 1);
                uint4 cv = make_uint4(CANARY, CANARY, CANARY, CANARY);
                asm volatile("st.global.cg.v4.u32 [%0], {%1,%2,%3,%4};"
                             :: "l"(cz), "r"(cv.x), "r"(cv.y), "r"(cv.z), "r"(cv.w) : "memory");
                asm volatile("st.global.cg.v4.u32 [%0], {%1,%2,%3,%4};"
                             :: "l"(cz + 4), "r"(cv.x), "r"(cv.y), "r"(cv.z), "r"(cv.w) : "memory");
            }
        } else if (wid == 1) {
            // ---- warp 1: lagged damped normalizer for step t+1 (off-path) ----
            const float4* m4 = (const float4*)(mxs[t & 1] + ln * 8);
            float4 a = m4[0], b4 = m4[1];
            float m = fmaxf(fmaxf(fmaxf(a.x, a.y), fmaxf(a.z, a.w)),
                            fmaxf(fmaxf(b4.x, b4.y), fmaxf(b4.z, b4.w)));
            #pragma unroll
            for (int off = 16; off; off >>= 1)
                m = fmaxf(m, __shfl_xor_sync(0xffffffffu, m, off));
            if (ln == 0 && t < S - 1) {
                float lr = 0.5f * __logf(m);        // bit-identical in every CTA
                sNorm[(t + 1) & 1] = __expf(-lr);
                L += (double)lr;                    // tid 32
            }
        }
        // no loop-end sync: free-running warps write only part[] (readers all
        // pre-sync#2) and mxs[(t+1)&1] (warp 1 reads mxs[t&1]) before sync#1
        // of t+1, which warps 0/1 join only after their epilogue. Race-free.
    }

    if (tid == 32) sL = L;

    // ---- terminal: logZ = log(sum_j W_S[j]*exp(tr[END,j])) + L ----
    if (b == 0) {
        uint4 wv = wait16B(g_W[S & 7] + wslot, (unsigned)NBLK * (unsigned)S);
        const float* te = trans + (size_t)END_IDX * T + c0;
        float p =
            __uint_as_float(wv.x << 16)        * __expf(te[0]) +
            __uint_as_float(wv.x & 0xffff0000u)* __expf(te[1]) +
            __uint_as_float(wv.y << 16)        * __expf(te[2]) +
            __uint_as_float(wv.y & 0xffff0000u)* __expf(te[3]) +
            __uint_as_float(wv.z << 16)        * __expf(te[4]) +
            __uint_as_float(wv.z & 0xffff0000u)* __expf(te[5]) +
            __uint_as_float(wv.w << 16)        * __expf(te[6]) +
            __uint_as_float(wv.w & 0xffff0000u)* __expf(te[7]);
        #pragma unroll
        for (int off = 16; off; off >>= 1)
            p += __shfl_xor_sync(0xffffffffu, p, off);
        __syncthreads();
        if (ln == 0) part[wid] = p;
        __syncthreads();
        if (tid == 0) {
            float tot = 0.0f;
            #pragma unroll
            for (int k = 0; k < 8; k++) tot += part[k];
            out[0] = __logf(tot) + (float)sL;
        }
    }
}

extern "C" void kernel_launch(void* const* d_in, const int* in_sizes, int n_in,
                              void* d_out, int out_size) {
    const float* h = (const float*)d_in[0];
    const float* trans = (const float*)d_in[1];
    float* out = (float*)d_out;
    int S = in_sizes[0] / T;

    crf_init<<<512, 256>>>(trans);
    crf_main<<<NBLK, NTHR>>>(h, trans, out, S);
}

// round 15
// speedup vs baseline: 4.3964x; 1.8757x over previous
#include <cuda_runtime.h>
#include <cuda_bf16.h>
#include <cstdint>

// CRF forward scan, exp domain. 128 persistent CTAs. (R9 topology — measured
// local optimum.)
// Fast path: consumers poll their OWN 16B of the bf16 W slot ring with ld.cv
// until no 16-bit half has the sign bit set (canary 0xFFC0). Detect == data
// load: ONE L2 round trip, no pre-dot barrier.
// R14: depth-2 SCOREBOARD-THROTTLED poll — two ld.cv in flight, alternate
// check/reissue. The check's scoreboard wait paces the loop at ~RT/2 per poll
// with ZERO issued backoff instructions (R13 showed ALU-chain backoff steals
// issue slots chip-wide) and ZERO nanosleep (suspected coarse-granularity tax
// in R9). Liveness: bounded tries + release-counter fallback (hang-free, R9).
// Normalizer: lagged sqrt-damped max by warp 1, fully off the critical path.

#define T 2048
#define ROWS 16
#define NBLK 128
#define NTHR 256
#define DEPTH 8
#define START_IDX 0
#define END_IDX 1
#define CANARY 0xFFC0FFC0u
#define POLL_TRIES 64

__device__ __align__(16) float g_Ef[(size_t)T * T];        // 16 MB exp(transitions)
__device__ __align__(16) unsigned g_W[DEPTH][T / 2];        // bf16-pair slot ring
__device__ unsigned g_cnt;                                  // fallback counter

typedef unsigned long long ull;

__device__ __forceinline__ ull pack2f(float a, float b) {
    ull r; asm("mov.b64 %0, {%1, %2};" : "=l"(r) : "f"(a), "f"(b)); return r;
}
__device__ __forceinline__ ull pack2u(unsigned a, unsigned b) {
    ull r; asm("mov.b64 %0, {%1, %2};" : "=l"(r) : "r"(a), "r"(b)); return r;
}
__device__ __forceinline__ void unpack2f(ull p, float& a, float& b) {
    asm("mov.b64 {%0, %1}, %2;" : "=f"(a), "=f"(b) : "l"(p));
}
#define FMA2(acc, a, b) \
    asm("fma.rn.f32x2 %0, %1, %2, %0;" : "+l"(acc) : "l"(a), "l"(b))

__device__ __forceinline__ uint4 ld16cv(const unsigned* p) {
    uint4 w;
    asm volatile("ld.global.cv.v4.u32 {%0,%1,%2,%3}, [%4];"
                 : "=r"(w.x), "=r"(w.y), "=r"(w.z), "=r"(w.w) : "l"(p));
    return w;
}
__device__ __forceinline__ bool clean16(uint4 w) {
    return ((w.x | w.y | w.z | w.w) & 0x80008000u) == 0u;
}

// Depth-2 scoreboard-throttled canary poll + counter fallback. Terminates.
__device__ __forceinline__ uint4 wait16B(const unsigned* p, unsigned cnt_target) {
    uint4 a = ld16cv(p);
    if (clean16(a)) return a;          // common fast case: already published
    uint4 b = ld16cv(p);
    #pragma unroll 1
    for (int i = 0; i < POLL_TRIES; i++) {
        if (clean16(a)) return a;      // scoreboard wait paces the loop
        a = ld16cv(p);                 // reissue slot a
        if (clean16(b)) return b;
        b = ld16cv(p);                 // reissue slot b
    }
    if (clean16(a)) return a;
    if (clean16(b)) return b;
    // Fallback: counter proves all producer stores are gpu-visible.
    unsigned c;
    do {
        asm volatile("ld.acquire.gpu.global.u32 %0, [%1];" : "=r"(c) : "l"(&g_cnt));
        if (c < cnt_target) __nanosleep(64);
    } while (c < cnt_target);
    return ld16cv(p);
}

__global__ void crf_init(const float* __restrict__ trans) {
    size_t idx = (size_t)blockIdx.x * blockDim.x + threadIdx.x;
    size_t stride = (size_t)gridDim.x * blockDim.x;
    for (size_t i = idx; i < (size_t)T * T; i += stride)
        g_Ef[i] = __expf(trans[i]);
    if (idx < T / 2) {
        g_W[0][idx] = (idx == 0) ? 0x00003F80u : 0u;   // W_0: bf16(1.0) at tag 0
        #pragma unroll
        for (int s = 1; s < DEPTH; s++) g_W[s][idx] = CANARY;
    }
    if (idx == 0) g_cnt = 0u;
}

__global__ void __launch_bounds__(NTHR, 1)
crf_main(const float* __restrict__ h, const float* __restrict__ trans,
         float* __restrict__ out, int S) {
    __shared__ __align__(16) float part[ROWS * NTHR];   // 16KB
    __shared__ __align__(16) float tmp2[ROWS * 16];
    __shared__ __align__(16) float mxs[2][NTHR];        // parity double-buffer
    __shared__ float sNorm[2];
    __shared__ double sL;

    const int tid = threadIdx.x;
    const int wid = tid >> 5;
    const int ln = tid & 31;
    const int b = blockIdx.x;
    const int r0 = b * ROWS;
    const int c0 = wid * 256 + ln * 8;    // my 8 columns
    const int wslot = c0 >> 1;            // word offset of my 16B in a slot

    if (tid == 0) { sNorm[0] = 1.0f; sNorm[1] = 1.0f; }

    // E -> registers: rows r0..r0+15 x my 8 cols, packed f32x2
    ull e64[ROWS][4];
    #pragma unroll
    for (int r = 0; r < ROWS; r++) {
        const float4* ep = (const float4*)(g_Ef + (size_t)(r0 + r) * T + c0);
        float4 a = ep[0], bb = ep[1];
        e64[r][0] = pack2f(a.x, a.y);
        e64[r][1] = pack2f(a.z, a.w);
        e64[r][2] = pack2f(bb.x, bb.y);
        e64[r][3] = pack2f(bb.z, bb.w);
    }

    double L = 0.0;   // meaningful only in tid 32

    for (int t = 0; t < S; t++) {
        // emissions (exp'd) for my row — off-path
        float eem = 1.0f;
        if (tid < ROWS) eem = __expf(__ldg(&h[(size_t)t * T + r0 + tid]));

        // ---- wait for my own 16B of W_t (pipelined canary, safe fallback) ----
        uint4 wv = wait16B(g_W[t & 7] + wslot, (unsigned)NBLK * (unsigned)t);

        ull w64[4];
        w64[0] = pack2u(wv.x << 16, wv.x & 0xffff0000u);
        w64[1] = pack2u(wv.y << 16, wv.y & 0xffff0000u);
        w64[2] = pack2u(wv.z << 16, wv.z & 0xffff0000u);
        w64[3] = pack2u(wv.w << 16, wv.w & 0xffff0000u);
        {   // thread-local max for the off-path normalizer — parity buffer
            float m0 = fmaxf(__uint_as_float(wv.x << 16), __uint_as_float(wv.x & 0xffff0000u));
            float m1 = fmaxf(__uint_as_float(wv.y << 16), __uint_as_float(wv.y & 0xffff0000u));
            float m2 = fmaxf(__uint_as_float(wv.z << 16), __uint_as_float(wv.z & 0xffff0000u));
            float m3 = fmaxf(__uint_as_float(wv.w << 16), __uint_as_float(wv.w & 0xffff0000u));
            mxs[t & 1][tid] = fmaxf(fmaxf(m0, m1), fmaxf(m2, m3));
        }

        // ---- dot: 16 rows x 8 cols, E in regs ----
        #pragma unroll
        for (int r = 0; r < ROWS; r++) {
            ull acc = 0ULL;
            FMA2(acc, e64[r][0], w64[0]);
            FMA2(acc, e64[r][1], w64[1]);
            FMA2(acc, e64[r][2], w64[2]);
            FMA2(acc, e64[r][3], w64[3]);
            float x, y;
            unpack2f(acc, x, y);
            part[r * NTHR + tid] = x + y;
        }
        __syncthreads();   // #1

        // ---- stage1: 256 partials/row -> 16/row ----
        {
            int rj = tid >> 4, cj = tid & 15;
            const float4* p4 = (const float4*)(part + rj * NTHR + cj * 16);
            float4 a = p4[0], b4 = p4[1], c4 = p4[2], d4 = p4[3];
            tmp2[rj * 16 + cj] =
                ((a.x + a.y) + (a.z + a.w)) + ((b4.x + b4.y) + (b4.z + b4.w)) +
                ((c4.x + c4.y) + (c4.z + c4.w)) + ((d4.x + d4.y) + (d4.z + d4.w));
        }
        __syncthreads();   // #2

        if (wid == 0) {
            if (ln < ROWS) {
                // ---- stage2: finish my row, scale, publish ----
                const float4* q4 = (const float4*)(tmp2 + ln * 16);
                float4 a = q4[0], b4 = q4[1], c4 = q4[2], d4 = q4[3];
                float rs =
                    ((a.x + a.y) + (a.z + a.w)) + ((b4.x + b4.y) + (b4.z + b4.w)) +
                    ((c4.x + c4.y) + (c4.z + c4.w)) + ((d4.x + d4.y) + (d4.z + d4.w));
                float n = rs * sNorm[t & 1] * eem;
                unsigned short us = __bfloat16_as_ushort(__float2bfloat16(n));
                unsigned short* dst = (unsigned short*)g_W[(t + 1) & 7] + (r0 + ln);
                asm volatile("st.global.cg.u16 [%0], %1;" :: "l"(dst), "h"(us) : "memory");
            }
            __syncwarp();   // order data stores before the release red
            if (ln == 16) {
                asm volatile("red.release.gpu.global.add.u32 [%0], %1;"
                             :: "l"(&g_cnt), "r"(1u) : "memory");
            } else if (ln == 17) {
                // clear my CTA's 32B in the slot holding W_{t-2}
                unsigned* cz = g_W[(t + 6) & 7] + (r0 >> 1);
                uint4 cv = make_uint4(CANARY, CANARY, CANARY, CANARY);
                asm volatile("st.global.cg.v4.u32 [%0], {%1,%2,%3,%4};"
                             :: "l"(cz), "r"(cv.x), "r"(cv.y), "r"(cv.z), "r"(cv.w) : "memory");
                asm volatile("st.global.cg.v4.u32 [%0], {%1,%2,%3,%4};"
                             :: "l"(cz + 4), "r"(cv.x), "r"(cv.y), "r"(cv.z), "r"(cv.w) : "memory");
            }
        } else if (wid == 1) {
            // ---- warp 1: lagged damped normalizer for step t+1 (off-path) ----
            const float4* m4 = (const float4*)(mxs[t & 1] + ln * 8);
            float4 a = m4[0], b4 = m4[1];
            float m = fmaxf(fmaxf(fmaxf(a.x, a.y), fmaxf(a.z, a.w)),
                            fmaxf(fmaxf(b4.x, b4.y), fmaxf(b4.z, b4.w)));
            #pragma unroll
            for (int off = 16; off; off >>= 1)
                m = fmaxf(m, __shfl_xor_sync(0xffffffffu, m, off));
            if (ln == 0 && t < S - 1) {
                float lr = 0.5f * __logf(m);        // bit-identical in every CTA
                sNorm[(t + 1) & 1] = __expf(-lr);
                L += (double)lr;                    // tid 32
            }
        }
        // no loop-end sync: free-running warps write only part[] (readers all
        // pre-sync#2) and mxs[(t+1)&1] (warp 1 reads mxs[t&1]) before sync#1
        // of t+1, which warps 0/1 join only after their epilogue. Race-free.
    }

    if (tid == 32) sL = L;

    // ---- terminal: logZ = log(sum_j W_S[j]*exp(tr[END,j])) + L ----
    if (b == 0) {
        uint4 wv = wait16B(g_W[S & 7] + wslot, (unsigned)NBLK * (unsigned)S);
        const float* te = trans + (size_t)END_IDX * T + c0;
        float p =
            __uint_as_float(wv.x << 16)        * __expf(te[0]) +
            __uint_as_float(wv.x & 0xffff0000u)* __expf(te[1]) +
            __uint_as_float(wv.y << 16)        * __expf(te[2]) +
            __uint_as_float(wv.y & 0xffff0000u)* __expf(te[3]) +
            __uint_as_float(wv.z << 16)        * __expf(te[4]) +
            __uint_as_float(wv.z & 0xffff0000u)* __expf(te[5]) +
            __uint_as_float(wv.w << 16)        * __expf(te[6]) +
            __uint_as_float(wv.w & 0xffff0000u)* __expf(te[7]);
        #pragma unroll
        for (int off = 16; off; off >>= 1)
            p += __shfl_xor_sync(0xffffffffu, p, off);
        __syncthreads();
        if (ln == 0) part[wid] = p;
        __syncthreads();
        if (tid == 0) {
            float tot = 0.0f;
            #pragma unroll
            for (int k = 0; k < 8; k++) tot += part[k];
            out[0] = __logf(tot) + (float)sL;
        }
    }
}

extern "C" void kernel_launch(void* const* d_in, const int* in_sizes, int n_in,
                              void* d_out, int out_size) {
    const float* h = (const float*)d_in[0];
    const float* trans = (const float*)d_in[1];
    float* out = (float*)d_out;
    int S = in_sizes[0] / T;

    crf_init<<<512, 256>>>(trans);
    crf_main<<<NBLK, NTHR>>>(h, trans, out, S);
}

// round 17
// speedup vs baseline: 4.6296x; 1.0530x over previous
#include <cuda_runtime.h>
#include <cuda_bf16.h>
#include <cstdint>

// CRF forward scan, exp domain. 128 persistent CTAs. (R14 = measured best.)
// Handoff: consumers poll their OWN 16B of the bf16 W slot ring with ld.cv
// until no 16-bit half has the sign bit set (canary 0xFFC0). Detect == data.
// R16: depth-3 scoreboard-throttled poll (~RT/3 granularity, zero issued
// backoff); bank-conflict-free smem reduce (stage1 stride-4 float4 gather,
// tmp2 padded stride 17 + scalar stage2); emissions prefetched 1 step ahead.
// Liveness: bounded tries + release-counter fallback (hang-free since R9).
// Normalizer: lagged sqrt-damped max by warp 1, fully off the critical path.

#define T 2048
#define ROWS 16
#define NBLK 128
#define NTHR 256
#define DEPTH 8
#define START_IDX 0
#define END_IDX 1
#define CANARY 0xFFC0FFC0u
#define POLL_TRIES 96
#define TMP2_STRIDE 17

__device__ __align__(16) float g_Ef[(size_t)T * T];        // 16 MB exp(transitions)
__device__ __align__(16) unsigned g_W[DEPTH][T / 2];        // bf16-pair slot ring
__device__ unsigned g_cnt;                                  // fallback counter

typedef unsigned long long ull;

__device__ __forceinline__ ull pack2f(float a, float b) {
    ull r; asm("mov.b64 %0, {%1, %2};" : "=l"(r) : "f"(a), "f"(b)); return r;
}
__device__ __forceinline__ ull pack2u(unsigned a, unsigned b) {
    ull r; asm("mov.b64 %0, {%1, %2};" : "=l"(r) : "r"(a), "r"(b)); return r;
}
__device__ __forceinline__ void unpack2f(ull p, float& a, float& b) {
    asm("mov.b64 {%0, %1}, %2;" : "=f"(a), "=f"(b) : "l"(p));
}
#define FMA2(acc, a, b) \
    asm("fma.rn.f32x2 %0, %1, %2, %0;" : "+l"(acc) : "l"(a), "l"(b))

__device__ __forceinline__ uint4 ld16cv(const unsigned* p) {
    uint4 w;
    asm volatile("ld.global.cv.v4.u32 {%0,%1,%2,%3}, [%4];"
                 : "=r"(w.x), "=r"(w.y), "=r"(w.z), "=r"(w.w) : "l"(p));
    return w;
}
__device__ __forceinline__ bool clean16(uint4 w) {
    return ((w.x | w.y | w.z | w.w) & 0x80008000u) == 0u;
}

// Depth-3 scoreboard-throttled canary poll + counter fallback. Terminates.
__device__ __forceinline__ uint4 wait16B(const unsigned* p, unsigned cnt_target) {
    uint4 a = ld16cv(p);
    if (clean16(a)) return a;          // common fast case: already published
    uint4 b = ld16cv(p);
    uint4 c = ld16cv(p);
    #pragma unroll 1
    for (int i = 0; i < POLL_TRIES; i++) {
        if (clean16(a)) return a;      // scoreboard wait paces the loop ~RT/3
        a = ld16cv(p);
        if (clean16(b)) return b;
        b = ld16cv(p);
        if (clean16(c)) return c;
        c = ld16cv(p);
    }
    if (clean16(a)) return a;
    if (clean16(b)) return b;
    if (clean16(c)) return c;
    // Fallback: counter proves all producer stores are gpu-visible.
    unsigned cc;
    do {
        asm volatile("ld.acquire.gpu.global.u32 %0, [%1];" : "=r"(cc) : "l"(&g_cnt));
        if (cc < cnt_target) __nanosleep(64);
    } while (cc < cnt_target);
    return ld16cv(p);
}

__global__ void crf_init(const float* __restrict__ trans) {
    size_t idx = (size_t)blockIdx.x * blockDim.x + threadIdx.x;
    size_t stride = (size_t)gridDim.x * blockDim.x;
    for (size_t i = idx; i < (size_t)T * T; i += stride)
        g_Ef[i] = __expf(trans[i]);
    if (idx < T / 2) {
        g_W[0][idx] = (idx == 0) ? 0x00003F80u : 0u;   // W_0: bf16(1.0) at tag 0
        #pragma unroll
        for (int s = 1; s < DEPTH; s++) g_W[s][idx] = CANARY;
    }
    if (idx == 0) g_cnt = 0u;
}

__global__ void __launch_bounds__(NTHR, 1)
crf_main(const float* __restrict__ h, const float* __restrict__ trans,
         float* __restrict__ out, int S) {
    __shared__ __align__(16) float part[ROWS * NTHR];       // 16KB
    __shared__ __align__(16) float tmp2[ROWS * TMP2_STRIDE];
    __shared__ __align__(16) float mxs[2][NTHR];            // parity buffers
    __shared__ float sNorm[2];
    __shared__ double sL;

    const int tid = threadIdx.x;
    const int wid = tid >> 5;
    const int ln = tid & 31;
    const int b = blockIdx.x;
    const int r0 = b * ROWS;
    const int c0 = wid * 256 + ln * 8;    // my 8 columns
    const int wslot = c0 >> 1;            // word offset of my 16B in a slot

    if (tid == 0) { sNorm[0] = 1.0f; sNorm[1] = 1.0f; }

    // E -> registers: rows r0..r0+15 x my 8 cols, packed f32x2
    ull e64[ROWS][4];
    #pragma unroll
    for (int r = 0; r < ROWS; r++) {
        const float4* ep = (const float4*)(g_Ef + (size_t)(r0 + r) * T + c0);
        float4 a = ep[0], bb = ep[1];
        e64[r][0] = pack2f(a.x, a.y);
        e64[r][1] = pack2f(a.z, a.w);
        e64[r][2] = pack2f(bb.x, bb.y);
        e64[r][3] = pack2f(bb.z, bb.w);
    }

    double L = 0.0;   // meaningful only in tid 32

    // emission prefetch: one full step ahead (register rotation)
    float em_cur = 0.0f;
    if (tid < ROWS) em_cur = __ldg(&h[r0 + tid]);

    for (int t = 0; t < S; t++) {
        float eem = 1.0f;
        if (tid < ROWS) {
            eem = __expf(em_cur);
            if (t + 1 < S) em_cur = __ldg(&h[(size_t)(t + 1) * T + r0 + tid]);
        }

        // ---- wait for my own 16B of W_t (pipelined canary, safe fallback) ----
        uint4 wv = wait16B(g_W[t & 7] + wslot, (unsigned)NBLK * (unsigned)t);

        ull w64[4];
        w64[0] = pack2u(wv.x << 16, wv.x & 0xffff0000u);
        w64[1] = pack2u(wv.y << 16, wv.y & 0xffff0000u);
        w64[2] = pack2u(wv.z << 16, wv.z & 0xffff0000u);
        w64[3] = pack2u(wv.w << 16, wv.w & 0xffff0000u);
        {   // thread-local max for the off-path normalizer — parity buffer
            float m0 = fmaxf(__uint_as_float(wv.x << 16), __uint_as_float(wv.x & 0xffff0000u));
            float m1 = fmaxf(__uint_as_float(wv.y << 16), __uint_as_float(wv.y & 0xffff0000u));
            float m2 = fmaxf(__uint_as_float(wv.z << 16), __uint_as_float(wv.z & 0xffff0000u));
            float m3 = fmaxf(__uint_as_float(wv.w << 16), __uint_as_float(wv.w & 0xffff0000u));
            mxs[t & 1][tid] = fmaxf(fmaxf(m0, m1), fmaxf(m2, m3));
        }

        // ---- dot: 16 rows x 8 cols, E in regs ----
        #pragma unroll
        for (int r = 0; r < ROWS; r++) {
            ull acc = 0ULL;
            FMA2(acc, e64[r][0], w64[0]);
            FMA2(acc, e64[r][1], w64[1]);
            FMA2(acc, e64[r][2], w64[2]);
            FMA2(acc, e64[r][3], w64[3]);
            float x, y;
            unpack2f(acc, x, y);
            part[r * NTHR + tid] = x + y;
        }
        __syncthreads();   // #1

        // ---- stage1: 256 partials/row -> 16/row (stride-4 float4 gather,
        //      2-way max conflict; regrouped sum identical in every CTA) ----
        {
            int rj = tid >> 4, cj = tid & 15;
            const float4* p4 = (const float4*)(part + rj * NTHR);
            float4 a = p4[cj + 0 * 16];
            float4 b4 = p4[cj + 1 * 16];
            float4 c4 = p4[cj + 2 * 16];
            float4 d4 = p4[cj + 3 * 16];
            tmp2[rj * TMP2_STRIDE + cj] =
                ((a.x + a.y) + (a.z + a.w)) + ((b4.x + b4.y) + (b4.z + b4.w)) +
                ((c4.x + c4.y) + (c4.z + c4.w)) + ((d4.x + d4.y) + (d4.z + d4.w));
        }
        __syncthreads();   // #2

        if (wid == 0) {
            if (ln < ROWS) {
                // ---- stage2: 16 scalar reads (conflict-free), scale, publish ----
                const float* q = tmp2 + ln * TMP2_STRIDE;
                float s0 = (q[0] + q[1]) + (q[2] + q[3]);
                float s1 = (q[4] + q[5]) + (q[6] + q[7]);
                float s2 = (q[8] + q[9]) + (q[10] + q[11]);
                float s3 = (q[12] + q[13]) + (q[14] + q[15]);
                float rs = (s0 + s1) + (s2 + s3);
                float n = rs * sNorm[t & 1] * eem;
                unsigned short us = __bfloat16_as_ushort(__float2bfloat16(n));
                unsigned short* dst = (unsigned short*)g_W[(t + 1) & 7] + (r0 + ln);
                asm volatile("st.global.cg.u16 [%0], %1;" :: "l"(dst), "h"(us) : "memory");
            }
            __syncwarp();   // order data stores before the release red
            if (ln == 16) {
                asm volatile("red.release.gpu.global.add.u32 [%0], %1;"
                             :: "l"(&g_cnt), "r"(1u) : "memory");
            } else if (ln == 17) {
                // clear my CTA's 32B in the slot holding W_{t-2}
                unsigned* cz = g_W[(t + 6) & 7] + (r0 >> 1);
                uint4 cv = make_uint4(CANARY, CANARY, CANARY, CANARY);
                asm volatile("st.global.cg.v4.u32 [%0], {%1,%2,%3,%4};"
                             :: "l"(cz), "r"(cv.x), "r"(cv.y), "r"(cv.z), "r"(cv.w) : "memory");
                asm volatile("st.global.cg.v4.u32 [%0], {%1,%2,%3,%4};"
                             :: "l"(cz + 4), "r"(cv.x), "r"(cv.y), "r"(cv.z), "r"(cv.w) : "memory");
            }
        } else if (wid == 1) {
            // ---- warp 1: lagged damped normalizer for step t+1 (off-path) ----
            const float4* m4 = (const float4*)(mxs[t & 1] + ln * 8);
            float4 a = m4[0], b4 = m4[1];
            float m = fmaxf(fmaxf(fmaxf(a.x, a.y), fmaxf(a.z, a.w)),
                            fmaxf(fmaxf(b4.x, b4.y), fmaxf(b4.z, b4.w)));
            #pragma unroll
            for (int off = 16; off; off >>= 1)
                m = fmaxf(m, __shfl_xor_sync(0xffffffffu, m, off));
            if (ln == 0 && t < S - 1) {
                float lr = 0.5f * __logf(m);        // bit-identical in every CTA
                sNorm[(t + 1) & 1] = __expf(-lr);
                L += (double)lr;                    // tid 32
            }
        }
        // no loop-end sync: free-running warps write only part[] (readers all
        // pre-sync#2) and mxs[(t+1)&1] (warp 1 reads mxs[t&1]) before sync#1
        // of t+1, which warps 0/1 join only after their epilogue. Race-free.
    }

    if (tid == 32) sL = L;

    // ---- terminal: logZ = log(sum_j W_S[j]*exp(tr[END,j])) + L ----
    if (b == 0) {
        uint4 wv = wait16B(g_W[S & 7] + wslot, (unsigned)NBLK * (unsigned)S);
        const float* te = trans + (size_t)END_IDX * T + c0;
        float p =
            __uint_as_float(wv.x << 16)        * __expf(te[0]) +
            __uint_as_float(wv.x & 0xffff0000u)* __expf(te[1]) +
            __uint_as_float(wv.y << 16)        * __expf(te[2]) +
            __uint_as_float(wv.y & 0xffff0000u)* __expf(te[3]) +
            __uint_as_float(wv.z << 16)        * __expf(te[4]) +
            __uint_as_float(wv.z & 0xffff0000u)* __expf(te[5]) +
            __uint_as_float(wv.w << 16)        * __expf(te[6]) +
            __uint_as_float(wv.w & 0xffff0000u)* __expf(te[7]);
        #pragma unroll
        for (int off = 16; off; off >>= 1)
            p += __shfl_xor_sync(0xffffffffu, p, off);
        __syncthreads();
        if (ln == 0) part[wid] = p;
        __syncthreads();
        if (tid == 0) {
            float tot = 0.0f;
            #pragma unroll
            for (int k = 0; k < 8; k++) tot += part[k];
            out[0] = __logf(tot) + (float)sL;
        }
    }
}

extern "C" void kernel_launch(void* const* d_in, const int* in_sizes, int n_in,
                              void* d_out, int out_size) {
    const float* h = (const float*)d_in[0];
    const float* trans = (const float*)d_in[1];
    float* out = (float*)d_out;
    int S = in_sizes[0] / T;

    crf_init<<<512, 256>>>(trans);
    crf_main<<<NBLK, NTHR>>>(h, trans, out, S);
}